// round 1
// baseline (speedup 1.0000x reference)
#include <cuda_runtime.h>

#define SEQ 262144
#define HID 256

// Scratch (no allocs allowed): precomputed input drive and scan states.
__device__ float4 g_c[SEQ];   // 2*log2(e) * (B u_t + bA), per t
__device__ float4 g_x[SEQ];   // membrane potentials x_t (post-update), per t

__device__ __forceinline__ float ex2f(float x) {
    float y; asm("ex2.approx.f32 %0, %1;" : "=f"(y) : "f"(x)); return y;
}
__device__ __forceinline__ float rcpf(float x) {
    float y; asm("rcp.approx.f32 %0, %1;" : "=f"(y) : "f"(x)); return y;
}

// ---------------------------------------------------------------------------
// Kernel 1: fully parallel precompute of c_t = K*(B u_t + bA), K = 2*log2(e)
// ---------------------------------------------------------------------------
__global__ void prep_kernel(const float* __restrict__ u,
                            const float* __restrict__ B,
                            const float* __restrict__ bA) {
    int t = blockIdx.x * blockDim.x + threadIdx.x;
    if (t >= SEQ) return;
    const float K = 2.8853900817779268f;  // 2*log2(e)
    float u0 = u[t], u1 = u[SEQ + t], u2 = u[2 * SEQ + t];
    float c0 = K * (fmaf(B[0], u0, fmaf(B[1], u1, fmaf(B[2], u2, bA[0]))));
    float c1 = K * (fmaf(B[3], u0, fmaf(B[4], u1, fmaf(B[5], u2, bA[1]))));
    float c2 = K * (fmaf(B[6], u0, fmaf(B[7], u1, fmaf(B[8], u2, bA[2]))));
    g_c[t] = make_float4(c0, c1, c2, 0.f);
}

// ---------------------------------------------------------------------------
// Kernel 2: serial Euler scan, single thread, all state in registers.
// x_{t+1} = x_t + dt * tanh(A x_t + B u_t + bA)
// tanh(z) = 1 - 2 / (1 + 2^(2*log2(e)*z))  via ex2.approx + rcp.approx.
// K and A are pre-folded: w_i = (K*A)_i . x + c_i
// ---------------------------------------------------------------------------
__global__ void scan_kernel(const float* __restrict__ A,
                            const float* __restrict__ dtp) {
    if (threadIdx.x != 0 || blockIdx.x != 0) return;
    const float K = 2.8853900817779268f;
    const float dt = dtp[0];
    const float a00 = K * A[0], a01 = K * A[1], a02 = K * A[2];
    const float a10 = K * A[3], a11 = K * A[4], a12 = K * A[5];
    const float a20 = K * A[6], a21 = K * A[7], a22 = K * A[8];

    float x0 = 0.f, x1 = 0.f, x2 = 0.f;

    for (int t = 0; t < SEQ; t += 8) {
        float4 cv[8];
#pragma unroll
        for (int k = 0; k < 8; k++) cv[k] = g_c[t + k];
#pragma unroll
        for (int k = 0; k < 8; k++) {
            float w0 = fmaf(a00, x0, fmaf(a01, x1, fmaf(a02, x2, cv[k].x)));
            float w1 = fmaf(a10, x0, fmaf(a11, x1, fmaf(a12, x2, cv[k].y)));
            float w2 = fmaf(a20, x0, fmaf(a21, x1, fmaf(a22, x2, cv[k].z)));
            float T0 = fmaf(-2.f, rcpf(ex2f(w0) + 1.f), 1.f);
            float T1 = fmaf(-2.f, rcpf(ex2f(w1) + 1.f), 1.f);
            float T2 = fmaf(-2.f, rcpf(ex2f(w2) + 1.f), 1.f);
            x0 = fmaf(dt, T0, x0);
            x1 = fmaf(dt, T1, x1);
            x2 = fmaf(dt, T2, x2);
            g_x[t + k] = make_float4(x0, x1, x2, 0.f);
        }
    }
}

// ---------------------------------------------------------------------------
// Kernel 3: fully parallel MLP over timesteps.
// h = relu(W1 x + b1); out = W2 h + b2. Also transposes g_x into the
// membrane section of d_out. 4 timesteps per thread, weights in smem.
// ---------------------------------------------------------------------------
__global__ void mlp_kernel(const float* __restrict__ W1,
                           const float* __restrict__ b1,
                           const float* __restrict__ W2,
                           const float* __restrict__ b2,
                           float* __restrict__ out) {
    __shared__ float sW1[3 * HID];
    __shared__ float sW2[3 * HID];
    __shared__ float sb1[HID];
    __shared__ float sb2[4];

    for (int i = threadIdx.x; i < 3 * HID; i += blockDim.x) {
        sW1[i] = W1[i];
        sW2[i] = W2[i];
    }
    for (int i = threadIdx.x; i < HID; i += blockDim.x) sb1[i] = b1[i];
    if (threadIdx.x < 3) sb2[threadIdx.x] = b2[threadIdx.x];
    __syncthreads();

    int tid = blockIdx.x * blockDim.x + threadIdx.x;
    int t = tid * 4;
    if (t >= SEQ) return;

    float xs0[4], xs1[4], xs2[4];
#pragma unroll
    for (int k = 0; k < 4; k++) {
        float4 v = g_x[t + k];
        xs0[k] = v.x; xs1[k] = v.y; xs2[k] = v.z;
    }

    float acc0[4], acc1[4], acc2[4];
#pragma unroll
    for (int k = 0; k < 4; k++) {
        acc0[k] = sb2[0]; acc1[k] = sb2[1]; acc2[k] = sb2[2];
    }

#pragma unroll 4
    for (int j = 0; j < HID; j++) {
        float w10 = sW1[3 * j], w11 = sW1[3 * j + 1], w12 = sW1[3 * j + 2];
        float bj = sb1[j];
        float v0 = sW2[j], v1 = sW2[HID + j], v2 = sW2[2 * HID + j];
#pragma unroll
        for (int k = 0; k < 4; k++) {
            float h = fmaf(w10, xs0[k], fmaf(w11, xs1[k], fmaf(w12, xs2[k], bj)));
            h = fmaxf(h, 0.f);
            acc0[k] = fmaf(v0, h, acc0[k]);
            acc1[k] = fmaf(v1, h, acc1[k]);
            acc2[k] = fmaf(v2, h, acc2[k]);
        }
    }

    float* mem = out + 3 * SEQ;
    *reinterpret_cast<float4*>(out + 0 * SEQ + t) = make_float4(acc0[0], acc0[1], acc0[2], acc0[3]);
    *reinterpret_cast<float4*>(out + 1 * SEQ + t) = make_float4(acc1[0], acc1[1], acc1[2], acc1[3]);
    *reinterpret_cast<float4*>(out + 2 * SEQ + t) = make_float4(acc2[0], acc2[1], acc2[2], acc2[3]);
    *reinterpret_cast<float4*>(mem + 0 * SEQ + t) = make_float4(xs0[0], xs0[1], xs0[2], xs0[3]);
    *reinterpret_cast<float4*>(mem + 1 * SEQ + t) = make_float4(xs1[0], xs1[1], xs1[2], xs1[3]);
    *reinterpret_cast<float4*>(mem + 2 * SEQ + t) = make_float4(xs2[0], xs2[1], xs2[2], xs2[3]);
}

// ---------------------------------------------------------------------------
extern "C" void kernel_launch(void* const* d_in, const int* in_sizes, int n_in,
                              void* d_out, int out_size) {
    const float* u  = (const float*)d_in[0];
    const float* dt = (const float*)d_in[1];
    const float* A  = (const float*)d_in[2];
    const float* B  = (const float*)d_in[3];
    const float* bA = (const float*)d_in[4];
    const float* W1 = (const float*)d_in[5];
    const float* b1 = (const float*)d_in[6];
    const float* W2 = (const float*)d_in[7];
    const float* b2 = (const float*)d_in[8];
    float* out = (float*)d_out;

    prep_kernel<<<SEQ / 256, 256>>>(u, B, bA);
    scan_kernel<<<1, 32>>>(A, dt);
    mlp_kernel<<<SEQ / 4 / 128, 128>>>(W1, b1, W2, b2, out);
}